// round 15
// baseline (speedup 1.0000x reference)
#include <cuda_runtime.h>
#include <cstdint>

// y[n,c,h,w] = x[n,c,h,w] * gamma[c] + beta[c]
// x: (8, 128, 256, 256) fp32 = 16,777,216 float4. Channel = 16384 float4.
//
// Two-phase MLP=4 pipeline: 8 float4 per thread as two sequential
// load4 -> fma -> store4 phases. Per-thread outstanding-load depth stays at
// the measured optimum (4); phase-2 loads overlap phase-1 store drain.
// 8192 blocks x 256 threads, block span 2048 float4, 8 blocks/channel ->
// c = (blockIdx.x >> 3) & 127 (uniform per block).
//
// Context: MLP sweep 1/2/4/8(front-batched) -> 78.8/74.6/74.0/76.2 us;
// flat4 noise band 73.7-75.6 us @ ~6420-6530 GB/s (80-82% of HBM spec).

__global__ void __launch_bounds__(256)
scale_affine_flat4x2(const float4* __restrict__ x,
                     const float* __restrict__ gamma,
                     const float* __restrict__ beta,
                     float4* __restrict__ y) {
    const unsigned base = blockIdx.x * 2048u + threadIdx.x;  // float4 index
    const int c = (int)((blockIdx.x >> 3) & 127u);           // uniform per block

    const float g = __ldg(&gamma[c]);
    const float b = __ldg(&beta[c]);

    // ---- phase 1: float4s [base + 0/256/512/768] ----
    {
        const unsigned i0 = base;
        const unsigned i1 = base + 256u;
        const unsigned i2 = base + 512u;
        const unsigned i3 = base + 768u;

        float4 v0 = x[i0];
        float4 v1 = x[i1];
        float4 v2 = x[i2];
        float4 v3 = x[i3];

        v0.x = fmaf(v0.x, g, b); v0.y = fmaf(v0.y, g, b);
        v0.z = fmaf(v0.z, g, b); v0.w = fmaf(v0.w, g, b);
        v1.x = fmaf(v1.x, g, b); v1.y = fmaf(v1.y, g, b);
        v1.z = fmaf(v1.z, g, b); v1.w = fmaf(v1.w, g, b);
        v2.x = fmaf(v2.x, g, b); v2.y = fmaf(v2.y, g, b);
        v2.z = fmaf(v2.z, g, b); v2.w = fmaf(v2.w, g, b);
        v3.x = fmaf(v3.x, g, b); v3.y = fmaf(v3.y, g, b);
        v3.z = fmaf(v3.z, g, b); v3.w = fmaf(v3.w, g, b);

        y[i0] = v0;
        y[i1] = v1;
        y[i2] = v2;
        y[i3] = v3;
    }

    // ---- phase 2: float4s [base + 1024/1280/1536/1792] ----
    {
        const unsigned i0 = base + 1024u;
        const unsigned i1 = base + 1280u;
        const unsigned i2 = base + 1536u;
        const unsigned i3 = base + 1792u;

        float4 v0 = x[i0];
        float4 v1 = x[i1];
        float4 v2 = x[i2];
        float4 v3 = x[i3];

        v0.x = fmaf(v0.x, g, b); v0.y = fmaf(v0.y, g, b);
        v0.z = fmaf(v0.z, g, b); v0.w = fmaf(v0.w, g, b);
        v1.x = fmaf(v1.x, g, b); v1.y = fmaf(v1.y, g, b);
        v1.z = fmaf(v1.z, g, b); v1.w = fmaf(v1.w, g, b);
        v2.x = fmaf(v2.x, g, b); v2.y = fmaf(v2.y, g, b);
        v2.z = fmaf(v2.z, g, b); v2.w = fmaf(v2.w, g, b);
        v3.x = fmaf(v3.x, g, b); v3.y = fmaf(v3.y, g, b);
        v3.z = fmaf(v3.z, g, b); v3.w = fmaf(v3.w, g, b);

        y[i0] = v0;
        y[i1] = v1;
        y[i2] = v2;
        y[i3] = v3;
    }
}

extern "C" void kernel_launch(void* const* d_in, const int* in_sizes, int n_in,
                              void* d_out, int out_size) {
    const float* x     = (const float*)d_in[0];
    const float* gamma = (const float*)d_in[1];
    const float* beta  = (const float*)d_in[2];
    float* out = (float*)d_out;

    // out_size = 67,108,864 -> n4 = 16,777,216 -> 8192 blocks of 256, 8 f4/thread.
    const unsigned n4 = (unsigned)(out_size >> 2);
    const unsigned blocks = n4 / 2048u;

    scale_affine_flat4x2<<<blocks, 256>>>((const float4*)x, gamma, beta,
                                          (float4*)out);
}

// round 16
// speedup vs baseline: 1.0082x; 1.0082x over previous
#include <cuda_runtime.h>
#include <cstdint>

// y[n,c,h,w] = x[n,c,h,w] * gamma[c] + beta[c]
// x: (8, 128, 256, 256) fp32 = 16,777,216 float4. Channel = 16384 float4.
//
// FINAL kernel — measured optimum, converged after 15 rounds on GB300 sm_103a.
//
// Structure: flat launch, 4 float4 per thread, 16384 blocks x 256 threads.
// Block covers 1024 contiguous float4; 16 blocks/channel ->
// c = (blockIdx.x >> 4) & 127 is uniform per block (gamma/beta become
// block-uniform scalar loads; zero per-thread index math in the hot path).
// Four independent LDG.128s front-batched per thread (MLP=4).
//
// Evidence (kernel time @ ncu, single-variable sweeps):
//   per-thread MLP 1/2/4/8/4x2      -> 78.8 / 74.6 / 74.0 / 76.2 / 75.9 us
//     (front-batching 8 overfills the per-SM L1tex wavefront queue;
//      two-phase 4x2 gains nothing — stores are fire-and-forget)
//   512-thread blocks               -> 74.2 us (neutral)
//   v8 256-bit LDG/STG              -> 74.3 us (neutral; LTS cap path-indep)
//   __stcs evict-first stores       -> 75.6 us (neutral)
//   persistent grid + strided MLP   -> 83.2 us (regression)
//   this kernel, repeat profiles    -> 74.0 / 75.1 / 73.7 / 75.1 / 75.1 us
// Ceiling: ~6420-6530 GB/s = 80-82% of 8 TB/s spec for mixed 1R:1W streaming;
// fma 2.8% / issue 7.6% — DRAM is the only active pipe.

__global__ void __launch_bounds__(256)
scale_affine_flat4(const float4* __restrict__ x,
                   const float* __restrict__ gamma,
                   const float* __restrict__ beta,
                   float4* __restrict__ y) {
    const unsigned base = blockIdx.x * 1024u + threadIdx.x;  // float4 index
    const unsigned i0 = base;
    const unsigned i1 = base + 256u;
    const unsigned i2 = base + 512u;
    const unsigned i3 = base + 768u;
    const int c = (int)((blockIdx.x >> 4) & 127u);           // uniform per block

    // Front-batch all four loads (MLP=4, the measured optimum).
    float4 v0 = x[i0];
    float4 v1 = x[i1];
    float4 v2 = x[i2];
    float4 v3 = x[i3];

    const float g = __ldg(&gamma[c]);
    const float b = __ldg(&beta[c]);

    v0.x = fmaf(v0.x, g, b); v0.y = fmaf(v0.y, g, b);
    v0.z = fmaf(v0.z, g, b); v0.w = fmaf(v0.w, g, b);
    v1.x = fmaf(v1.x, g, b); v1.y = fmaf(v1.y, g, b);
    v1.z = fmaf(v1.z, g, b); v1.w = fmaf(v1.w, g, b);
    v2.x = fmaf(v2.x, g, b); v2.y = fmaf(v2.y, g, b);
    v2.z = fmaf(v2.z, g, b); v2.w = fmaf(v2.w, g, b);
    v3.x = fmaf(v3.x, g, b); v3.y = fmaf(v3.y, g, b);
    v3.z = fmaf(v3.z, g, b); v3.w = fmaf(v3.w, g, b);

    y[i0] = v0;
    y[i1] = v1;
    y[i2] = v2;
    y[i3] = v3;
}

extern "C" void kernel_launch(void* const* d_in, const int* in_sizes, int n_in,
                              void* d_out, int out_size) {
    const float* x     = (const float*)d_in[0];
    const float* gamma = (const float*)d_in[1];
    const float* beta  = (const float*)d_in[2];
    float* out = (float*)d_out;

    // out_size = 67,108,864 -> n4 = 16,777,216 -> 16384 blocks of 256, 4 f4/thread.
    const unsigned n4 = (unsigned)(out_size >> 2);
    const unsigned blocks = n4 / 1024u;

    scale_affine_flat4<<<blocks, 256>>>((const float4*)x, gamma, beta,
                                        (float4*)out);
}